// round 1
// baseline (speedup 1.0000x reference)
#include <cuda_runtime.h>
#include <math.h>

#define BB 2
#define SS 4096
#define DD 1024
#define HH 16
#define BLKSZ 64
#define NB 64          // S / BLK
#define GG 128         // num_global_tokens
#define NGB 2          // G / BLK
#define HDIM 64        // D / H
#define MROWS (BB*SS)  // 8192

// Scratch (device globals -- no allocation allowed)
__device__ float g_q[(size_t)BB*HH*SS*HDIM];
__device__ float g_k[(size_t)BB*HH*SS*HDIM];
__device__ float g_v[(size_t)BB*HH*SS*HDIM];
__device__ float g_ctx[(size_t)BB*SS*DD];

// ---------------------------------------------------------------------------
// QKV projection GEMM: tokens[8192,1024] @ W[1024,1024] -> head-split layout
// q[b,h,s,dd] = (tokens@W)[b*S+s, h*64+dd]
// Tile: BM=64, BN=64, BK=16; 256 threads; 4x4 register micro-tile.
// grid = (16, 128, 3); blockIdx.x == h (since BN==HDIM==64), z selects W/out.
// ---------------------------------------------------------------------------
__global__ __launch_bounds__(256) void qkv_gemm_kernel(
    const float* __restrict__ A,
    const float* __restrict__ W0,
    const float* __restrict__ W1,
    const float* __restrict__ W2)
{
    __shared__ __align__(16) float As[64][17];
    __shared__ __align__(16) float Bs[16][68];

    const float* W = (blockIdx.z == 0) ? W0 : ((blockIdx.z == 1) ? W1 : W2);
    float* Out = (blockIdx.z == 0) ? g_q : ((blockIdx.z == 1) ? g_k : g_v);

    const int t  = threadIdx.x;
    const int tx = t & 15;       // col group
    const int ty = t >> 4;       // row group
    const int m0 = blockIdx.y * 64;
    const int h  = blockIdx.x;
    const int n0 = h * 64;

    // load indices
    const int lr  = t >> 2;          // A row 0..63
    const int lk4 = (t & 3) * 4;     // A k offset
    const int bk  = t >> 4;          // B k row 0..15
    const int bc4 = (t & 15) * 4;    // B col offset

    float acc[4][4];
#pragma unroll
    for (int u = 0; u < 4; u++)
#pragma unroll
        for (int v = 0; v < 4; v++) acc[u][v] = 0.f;

    for (int k0 = 0; k0 < DD; k0 += 16) {
        float4 av = *(const float4*)(A + (size_t)(m0 + lr) * DD + k0 + lk4);
        As[lr][lk4 + 0] = av.x;
        As[lr][lk4 + 1] = av.y;
        As[lr][lk4 + 2] = av.z;
        As[lr][lk4 + 3] = av.w;
        float4 bv = *(const float4*)(W + (size_t)(k0 + bk) * DD + n0 + bc4);
        *(float4*)&Bs[bk][bc4] = bv;
        __syncthreads();
#pragma unroll
        for (int k = 0; k < 16; k++) {
            float a0 = As[ty * 4 + 0][k];
            float a1 = As[ty * 4 + 1][k];
            float a2 = As[ty * 4 + 2][k];
            float a3 = As[ty * 4 + 3][k];
            float4 b = *(const float4*)&Bs[k][tx * 4];
            acc[0][0] += a0 * b.x; acc[0][1] += a0 * b.y; acc[0][2] += a0 * b.z; acc[0][3] += a0 * b.w;
            acc[1][0] += a1 * b.x; acc[1][1] += a1 * b.y; acc[1][2] += a1 * b.z; acc[1][3] += a1 * b.w;
            acc[2][0] += a2 * b.x; acc[2][1] += a2 * b.y; acc[2][2] += a2 * b.z; acc[2][3] += a2 * b.w;
            acc[3][0] += a3 * b.x; acc[3][1] += a3 * b.y; acc[3][2] += a3 * b.z; acc[3][3] += a3 * b.w;
        }
        __syncthreads();
    }

#pragma unroll
    for (int u = 0; u < 4; u++) {
        int m  = m0 + ty * 4 + u;
        int b_ = m >> 12;          // /4096
        int s  = m & 4095;
        float* op = Out + (((size_t)(b_ * HH + h)) * SS + s) * HDIM + tx * 4;
        op[0] = acc[u][0]; op[1] = acc[u][1]; op[2] = acc[u][2]; op[3] = acc[u][3];
    }
}

// ---------------------------------------------------------------------------
// Output GEMM: g_ctx[8192,1024] @ Wu + bu -> out[8192,1024]
// ---------------------------------------------------------------------------
__global__ __launch_bounds__(256) void out_gemm_kernel(
    const float* __restrict__ W,
    const float* __restrict__ bias,
    float* __restrict__ Out)
{
    __shared__ __align__(16) float As[64][17];
    __shared__ __align__(16) float Bs[16][68];

    const float* A = g_ctx;
    const int t  = threadIdx.x;
    const int tx = t & 15;
    const int ty = t >> 4;
    const int m0 = blockIdx.y * 64;
    const int n0 = blockIdx.x * 64;

    const int lr  = t >> 2;
    const int lk4 = (t & 3) * 4;
    const int bk  = t >> 4;
    const int bc4 = (t & 15) * 4;

    float acc[4][4];
#pragma unroll
    for (int u = 0; u < 4; u++)
#pragma unroll
        for (int v = 0; v < 4; v++) acc[u][v] = 0.f;

    for (int k0 = 0; k0 < DD; k0 += 16) {
        float4 av = *(const float4*)(A + (size_t)(m0 + lr) * DD + k0 + lk4);
        As[lr][lk4 + 0] = av.x;
        As[lr][lk4 + 1] = av.y;
        As[lr][lk4 + 2] = av.z;
        As[lr][lk4 + 3] = av.w;
        float4 bv = *(const float4*)(W + (size_t)(k0 + bk) * DD + n0 + bc4);
        *(float4*)&Bs[bk][bc4] = bv;
        __syncthreads();
#pragma unroll
        for (int k = 0; k < 16; k++) {
            float a0 = As[ty * 4 + 0][k];
            float a1 = As[ty * 4 + 1][k];
            float a2 = As[ty * 4 + 2][k];
            float a3 = As[ty * 4 + 3][k];
            float4 b = *(const float4*)&Bs[k][tx * 4];
            acc[0][0] += a0 * b.x; acc[0][1] += a0 * b.y; acc[0][2] += a0 * b.z; acc[0][3] += a0 * b.w;
            acc[1][0] += a1 * b.x; acc[1][1] += a1 * b.y; acc[1][2] += a1 * b.z; acc[1][3] += a1 * b.w;
            acc[2][0] += a2 * b.x; acc[2][1] += a2 * b.y; acc[2][2] += a2 * b.z; acc[2][3] += a2 * b.w;
            acc[3][0] += a3 * b.x; acc[3][1] += a3 * b.y; acc[3][2] += a3 * b.z; acc[3][3] += a3 * b.w;
        }
        __syncthreads();
    }

    float bv0 = bias[n0 + tx * 4 + 0];
    float bv1 = bias[n0 + tx * 4 + 1];
    float bv2 = bias[n0 + tx * 4 + 2];
    float bv3 = bias[n0 + tx * 4 + 3];
#pragma unroll
    for (int u = 0; u < 4; u++) {
        int m = m0 + ty * 4 + u;
        float* op = Out + (size_t)m * DD + n0 + tx * 4;
        op[0] = acc[u][0] + bv0;
        op[1] = acc[u][1] + bv1;
        op[2] = acc[u][2] + bv2;
        op[3] = acc[u][3] + bv3;
    }
}

// ---------------------------------------------------------------------------
// BigBird sparse attention, flash-style streaming softmax.
// One CTA per (qblock, head, batch). 256 threads.
// Thread t: row r = t>>2, lane-in-row j = t&3, handles score cols / dims
// c = j + 4*i (i = 0..15).
// Key tile schedule:
//   qb < 2        : tiles 0..63 (full attention), to_mask
//   qb == 2       : blocks {0,1,2,3,4}, to_mask
//   3 <= qb <= 62 : blocks {0,1, qb-1, qb, qb+1}; global -> to_mask,
//                   window tiles -> band_mask[b, qb-3, r, w*64+c]
//   qb == 63      : blocks {0,1,61,62,63}, to_mask
// Writes ctx[b, s, h, dd] (ready for output GEMM) scaled by from_mask.
// ---------------------------------------------------------------------------
#define QS_STRIDE 65
#define KS_STRIDE 67
#define ATTN_SMEM_FLOATS (64 * QS_STRIDE + 3 * 64 * KS_STRIDE)
#define ATTN_SMEM_BYTES (ATTN_SMEM_FLOATS * 4)

__global__ __launch_bounds__(256) void attn_kernel(
    const float* __restrict__ band_mask,
    const float* __restrict__ from_mask,
    const float* __restrict__ to_mask)
{
    extern __shared__ float sm[];
    float* Qs = sm;                        // 64 x 65
    float* Ks = Qs + 64 * QS_STRIDE;       // 64 x 67
    float* Vs = Ks + 64 * KS_STRIDE;       // 64 x 67
    float* Ps = Vs + 64 * KS_STRIDE;       // 64 x 67

    const int qb = blockIdx.x;
    const int h  = blockIdx.y;
    const int b  = blockIdx.z;
    const int t  = threadIdx.x;
    const int r  = t >> 2;
    const int j  = t & 3;

    const float rs  = 0.125f;   // 1/sqrt(64)
    const float pen = -10000.f;

    // Load Q tile (64 x 64)
    {
        const float* qptr = g_q + (((size_t)(b * HH + h)) * SS + qb * BLKSZ) * HDIM;
        for (int i = t; i < 64 * 16; i += 256) {
            int row = i >> 4;
            int c4  = (i & 15) << 2;
            float4 v = *(const float4*)(qptr + row * HDIM + c4);
            float* dst = Qs + row * QS_STRIDE + c4;
            dst[0] = v.x; dst[1] = v.y; dst[2] = v.z; dst[3] = v.w;
        }
    }

    // Key-block schedule
    int nt;
    int kbs[5];
    bool is_band;   // window tiles (it>=2) of middle blocks use band_mask
    if (qb < NGB) {
        nt = NB; is_band = false;
    } else if (qb == NGB) {
        nt = 5; kbs[0] = 0; kbs[1] = 1; kbs[2] = 2; kbs[3] = 3; kbs[4] = 4;
        is_band = false;
    } else if (qb == NB - 1) {
        nt = 5; kbs[0] = 0; kbs[1] = 1; kbs[2] = 61; kbs[3] = 62; kbs[4] = 63;
        is_band = false;
    } else {
        nt = 5; kbs[0] = 0; kbs[1] = 1; kbs[2] = qb - 1; kbs[3] = qb; kbs[4] = qb + 1;
        is_band = true;
    }

    float m_r = -1e30f;
    float l_r = 0.f;
    float accv[16];
#pragma unroll
    for (int i = 0; i < 16; i++) accv[i] = 0.f;

    const size_t bh_base = ((size_t)(b * HH + h)) * SS;

    for (int it = 0; it < nt; it++) {
        int kb = (qb < NGB) ? it : kbs[it];

        // Load K and V tiles (64 x 64 each)
        const float* kptr = g_k + (bh_base + kb * BLKSZ) * HDIM;
        const float* vptr = g_v + (bh_base + kb * BLKSZ) * HDIM;
        for (int i = t; i < 64 * 16; i += 256) {
            int row = i >> 4;
            int c4  = (i & 15) << 2;
            float4 kv = *(const float4*)(kptr + row * HDIM + c4);
            float4 vv = *(const float4*)(vptr + row * HDIM + c4);
            float* kd = Ks + row * KS_STRIDE + c4;
            float* vd = Vs + row * KS_STRIDE + c4;
            kd[0] = kv.x; kd[1] = kv.y; kd[2] = kv.z; kd[3] = kv.w;
            vd[0] = vv.x; vd[1] = vv.y; vd[2] = vv.z; vd[3] = vv.w;
        }
        __syncthreads();

        // Scores: p[i] = Q[r,:] . K[j+4i,:]
        float p[16];
#pragma unroll
        for (int i = 0; i < 16; i++) p[i] = 0.f;
#pragma unroll 8
        for (int dd = 0; dd < 64; dd++) {
            float qv = Qs[r * QS_STRIDE + dd];
#pragma unroll
            for (int i = 0; i < 16; i++) {
                p[i] += qv * Ks[(j + 4 * i) * KS_STRIDE + dd];
            }
        }

        // Mask + scale
        bool band_tile = (is_band && it >= 2);
        const float* bm_row = band_tile
            ? band_mask + (((size_t)(b * 60 + (qb - 3)) * 64 + r) * 192 + (it - 2) * 64)
            : nullptr;
#pragma unroll
        for (int i = 0; i < 16; i++) {
            int c = j + 4 * i;
            float mk;
            if (band_tile) {
                mk = bm_row[c];
            } else {
                mk = to_mask[(size_t)b * SS + kb * BLKSZ + c];
            }
            p[i] = p[i] * rs + (1.f - mk) * pen;
        }

        // Row max (across 4 lanes of the row group)
        float tm = p[0];
#pragma unroll
        for (int i = 1; i < 16; i++) tm = fmaxf(tm, p[i]);
        tm = fmaxf(tm, __shfl_xor_sync(0xffffffffu, tm, 1));
        tm = fmaxf(tm, __shfl_xor_sync(0xffffffffu, tm, 2));

        float newm = fmaxf(m_r, tm);
        float corr = __expf(m_r - newm);
        float ts = 0.f;
#pragma unroll
        for (int i = 0; i < 16; i++) {
            float e = __expf(p[i] - newm);
            Ps[r * KS_STRIDE + j + 4 * i] = e;
            ts += e;
        }
        ts += __shfl_xor_sync(0xffffffffu, ts, 1);
        ts += __shfl_xor_sync(0xffffffffu, ts, 2);
        l_r = l_r * corr + ts;
        m_r = newm;
#pragma unroll
        for (int i = 0; i < 16; i++) accv[i] *= corr;
        __syncwarp();

        // AV: acc[dd = j+4i] += sum_c P[r,c] * V[c, dd]
#pragma unroll 8
        for (int c = 0; c < 64; c++) {
            float pv = Ps[r * KS_STRIDE + c];
#pragma unroll
            for (int i = 0; i < 16; i++) {
                accv[i] += pv * Vs[c * KS_STRIDE + j + 4 * i];
            }
        }
        __syncthreads();
    }

    // Write ctx[b, s, h, dd] * from_mask / l
    int s = qb * BLKSZ + r;
    float fm  = from_mask[(size_t)b * SS + s];
    float inv = fm / l_r;
    float* cptr = g_ctx + (((size_t)b * SS + s) * HH + h) * HDIM;
#pragma unroll
    for (int i = 0; i < 16; i++) {
        cptr[j + 4 * i] = accv[i] * inv;
    }
}

// ---------------------------------------------------------------------------
extern "C" void kernel_launch(void* const* d_in, const int* in_sizes, int n_in,
                              void* d_out, int out_size)
{
    const float* tokens    = (const float*)d_in[0];
    const float* band_mask = (const float*)d_in[1];
    const float* from_mask = (const float*)d_in[2];
    const float* to_mask   = (const float*)d_in[3];
    const float* Wq        = (const float*)d_in[4];
    const float* Wk        = (const float*)d_in[5];
    const float* Wv        = (const float*)d_in[6];
    const float* Wu        = (const float*)d_in[7];
    const float* bu        = (const float*)d_in[8];
    float* out = (float*)d_out;

    cudaFuncSetAttribute(attn_kernel,
                         cudaFuncAttributeMaxDynamicSharedMemorySize,
                         ATTN_SMEM_BYTES);

    // 1) QKV projections (fused into one launch via grid.z)
    qkv_gemm_kernel<<<dim3(16, 128, 3), 256>>>(tokens, Wq, Wk, Wv);

    // 2) Sparse attention
    attn_kernel<<<dim3(NB, HH, BB), 256, ATTN_SMEM_BYTES>>>(band_mask, from_mask, to_mask);

    // 3) Output projection + bias
    out_gemm_kernel<<<dim3(16, 128), 256>>>(Wu, bu, out);
}

// round 3
// speedup vs baseline: 2.7373x; 2.7373x over previous
#include <cuda_runtime.h>
#include <cuda_bf16.h>
#include <cstdint>
#include <math.h>

#define BB 2
#define SS 4096
#define DD 1024
#define HH 16
#define BLKSZ 64
#define NB 64          // S / BLK
#define NGB 2          // G / BLK
#define HDIM 64        // D / H
#define MROWS (BB*SS)  // 8192

// ---------------------------------------------------------------------------
// Device scratch (no allocation allowed)
// ---------------------------------------------------------------------------
__device__ __nv_bfloat16 g_x_hi[(size_t)MROWS*DD];
__device__ __nv_bfloat16 g_x_lo[(size_t)MROWS*DD];
__device__ __nv_bfloat16 g_c_hi[(size_t)MROWS*DD];
__device__ __nv_bfloat16 g_c_lo[(size_t)MROWS*DD];
__device__ __nv_bfloat16 g_w_hi[(size_t)4*DD*DD];   // [w][k][n] (native layout)
__device__ __nv_bfloat16 g_w_lo[(size_t)4*DD*DD];
__device__ float g_q[(size_t)BB*HH*SS*HDIM];
__device__ float g_k[(size_t)BB*HH*SS*HDIM];
__device__ float g_v[(size_t)BB*HH*SS*HDIM];

// ---------------------------------------------------------------------------
// mma.sync / ldmatrix helpers (generic sm_80+ PTX -- compiles for sm_103)
// ---------------------------------------------------------------------------
__device__ __forceinline__ uint32_t smem_u32(const void* p) {
    uint32_t a;
    asm("{ .reg .u64 t; cvta.to.shared.u64 t, %1; cvt.u32.u64 %0, t; }" : "=r"(a) : "l"(p));
    return a;
}
__device__ __forceinline__ void ldsm_x4(uint32_t (&r)[4], uint32_t addr) {
    asm volatile("ldmatrix.sync.aligned.m8n8.x4.shared.b16 {%0,%1,%2,%3}, [%4];"
        : "=r"(r[0]), "=r"(r[1]), "=r"(r[2]), "=r"(r[3]) : "r"(addr));
}
__device__ __forceinline__ void ldsm_x2_trans(uint32_t (&r)[2], uint32_t addr) {
    asm volatile("ldmatrix.sync.aligned.m8n8.x2.trans.shared.b16 {%0,%1}, [%2];"
        : "=r"(r[0]), "=r"(r[1]) : "r"(addr));
}
__device__ __forceinline__ void mma_bf16(float (&c)[4], const uint32_t (&a)[4],
                                         const uint32_t (&b)[2]) {
    asm volatile("mma.sync.aligned.m16n8k16.row.col.f32.bf16.bf16.f32 "
        "{%0,%1,%2,%3}, {%4,%5,%6,%7}, {%8,%9}, {%0,%1,%2,%3};"
        : "+f"(c[0]), "+f"(c[1]), "+f"(c[2]), "+f"(c[3])
        : "r"(a[0]), "r"(a[1]), "r"(a[2]), "r"(a[3]), "r"(b[0]), "r"(b[1]));
}

// ---------------------------------------------------------------------------
// Split tokens into bf16 hi/lo (row-major [8192, 1024])
// ---------------------------------------------------------------------------
__global__ __launch_bounds__(256) void split_x_kernel(const float* __restrict__ X)
{
    size_t i = (size_t)blockIdx.x * 256 + threadIdx.x;
    float4 v = ((const float4*)X)[i];
    float vs[4] = {v.x, v.y, v.z, v.w};
#pragma unroll
    for (int j = 0; j < 4; j++) {
        __nv_bfloat16 hi = __float2bfloat16(vs[j]);
        float lo = vs[j] - __bfloat162float(hi);
        g_x_hi[i * 4 + j] = hi;
        g_x_lo[i * 4 + j] = __float2bfloat16(lo);
    }
}

// ---------------------------------------------------------------------------
// Elementwise weight split (keeps native [k][n] layout -- mma.row.col wants it)
// grid (1024, 4), block 256 -- each handles one float4 of one weight
// ---------------------------------------------------------------------------
__global__ __launch_bounds__(256) void wsplit_kernel(
    const float* __restrict__ Wq, const float* __restrict__ Wk,
    const float* __restrict__ Wv, const float* __restrict__ Wu)
{
    const int w = blockIdx.y;
    const float* W = (w == 0) ? Wq : (w == 1) ? Wk : (w == 2) ? Wv : Wu;
    size_t i = (size_t)blockIdx.x * 256 + threadIdx.x;     // float4 idx, 262144 total
    float4 v = ((const float4*)W)[i];
    float vs[4] = {v.x, v.y, v.z, v.w};
    size_t base = (size_t)w * DD * DD + i * 4;
#pragma unroll
    for (int j = 0; j < 4; j++) {
        __nv_bfloat16 hi = __float2bfloat16(vs[j]);
        float lo = vs[j] - __bfloat162float(hi);
        g_w_hi[base + j] = hi;
        g_w_lo[base + j] = __float2bfloat16(lo);
    }
}

// ---------------------------------------------------------------------------
// Split-bf16 HMMA GEMM: C[8192,1024] = A[8192,1024] @ W[1024,1024]
// CTA tile 128(M) x 128(N), K-chunk 64. 8 warps: warp_m = wid%4, warp_n = wid/4,
// warp tile 32x64 via m16n8k16 (2 m-frags x 8 n-frags x 4 k-frags).
// 3 split products per chunk: hi*hi + hi*lo + lo*hi, fp32 accumulators.
// mode 0/1/2: A = g_x, out = g_q/g_k/g_v head-split [b,h,s,64]
// mode 3:     A = g_c, out = d_out row-major + bias
// ---------------------------------------------------------------------------
#define SA_STR 72           // bf16 units (144B rows -> conflict-free ldmatrix)
#define SB_STR 136          // bf16 units (272B rows)
#define SA_HI 0
#define SA_LO (128*SA_STR)            // 9216
#define SB_HI (2*128*SA_STR)          // 18432
#define SB_LO (SB_HI + 64*SB_STR)     // 27136
#define GEMM_SMEM_B16 (SB_LO + 64*SB_STR)   // 35840 b16 = 71680 B
#define GEMM_SMEM_BYTES (GEMM_SMEM_B16 * 2)

__global__ __launch_bounds__(256) void gemm_hmma_kernel(
    int mode_base, const float* __restrict__ bias, float* __restrict__ out_ptr)
{
    extern __shared__ __align__(16) __nv_bfloat16 smem_bf[];
    const uint32_t smem_base = smem_u32(smem_bf);

    const int t    = threadIdx.x;
    const int lane = t & 31;
    const int wid  = t >> 5;
    const int wm   = wid & 3;           // 0..3  (M)
    const int wn   = wid >> 2;          // 0..1  (N)
    const int mode = mode_base + blockIdx.z;

    const int n0 = blockIdx.x * 128;
    const int m0 = blockIdx.y * 128;

    const __nv_bfloat16* Ahi = (mode < 3) ? g_x_hi : g_c_hi;
    const __nv_bfloat16* Alo = (mode < 3) ? g_x_lo : g_c_lo;
    const __nv_bfloat16* Bhi = g_w_hi + (size_t)mode * DD * DD;
    const __nv_bfloat16* Blo = g_w_lo + (size_t)mode * DD * DD;

    float acc[2][8][4];
#pragma unroll
    for (int mi = 0; mi < 2; mi++)
#pragma unroll
        for (int nj = 0; nj < 8; nj++)
#pragma unroll
            for (int e = 0; e < 4; e++) acc[mi][nj][e] = 0.f;

    const int lrow = lane & 15;
    const int lcol = (lane >> 4) * 8;

    for (int kc = 0; kc < 16; kc++) {
        const int k0 = kc * 64;
        // Fill A tiles (128 x 64 b16, hi & lo)
#pragma unroll
        for (int it2 = 0; it2 < 4; it2++) {
            int i = t + it2 * 256;
            int row = i >> 3, seg = (i & 7) * 8;
            size_t go = (size_t)(m0 + row) * DD + k0 + seg;
            *(uint4*)(smem_bf + SA_HI + row * SA_STR + seg) = *(const uint4*)(Ahi + go);
            *(uint4*)(smem_bf + SA_LO + row * SA_STR + seg) = *(const uint4*)(Alo + go);
        }
        // Fill B tiles (64 x 128 b16, hi & lo)
#pragma unroll
        for (int it2 = 0; it2 < 4; it2++) {
            int i = t + it2 * 256;
            int row = i >> 4, seg = (i & 15) * 8;
            size_t go = (size_t)(k0 + row) * DD + n0 + seg;
            *(uint4*)(smem_bf + SB_HI + row * SB_STR + seg) = *(const uint4*)(Bhi + go);
            *(uint4*)(smem_bf + SB_LO + row * SB_STR + seg) = *(const uint4*)(Blo + go);
        }
        __syncthreads();

#pragma unroll
        for (int kk = 0; kk < 4; kk++) {
            const int kb = kk * 16;
            uint32_t ah[2][4], al[2][4];
#pragma unroll
            for (int mi = 0; mi < 2; mi++) {
                uint32_t off = (uint32_t)(((wm * 32 + mi * 16 + lrow) * SA_STR + kb + lcol) * 2);
                ldsm_x4(ah[mi], smem_base + SA_HI * 2 + off);
                ldsm_x4(al[mi], smem_base + SA_LO * 2 + off);
            }
            uint32_t bh[8][2], bl[8][2];
#pragma unroll
            for (int nj = 0; nj < 8; nj++) {
                uint32_t off = (uint32_t)(((kb + lrow) * SB_STR + wn * 64 + nj * 8) * 2);
                ldsm_x2_trans(bh[nj], smem_base + SB_HI * 2 + off);
                ldsm_x2_trans(bl[nj], smem_base + SB_LO * 2 + off);
            }
#pragma unroll
            for (int mi = 0; mi < 2; mi++)
#pragma unroll
                for (int nj = 0; nj < 8; nj++) {
                    mma_bf16(acc[mi][nj], ah[mi], bh[nj]);
                    mma_bf16(acc[mi][nj], ah[mi], bl[nj]);
                    mma_bf16(acc[mi][nj], al[mi], bh[nj]);
                }
        }
        __syncthreads();
    }

    // Epilogue. Accum frag: c0,c1 = (row lane/4, cols 2*(lane%4)+{0,1});
    //                      c2,c3 = (row lane/4+8, same cols)
#pragma unroll
    for (int mi = 0; mi < 2; mi++) {
        const int r0 = m0 + wm * 32 + mi * 16 + (lane >> 2);
#pragma unroll
        for (int nj = 0; nj < 8; nj++) {
            const int col = wn * 64 + nj * 8 + (lane & 3) * 2;
            if (mode < 3) {
                float* Out = (mode == 0) ? g_q : (mode == 1) ? g_k : g_v;
                const int h  = (n0 + col) >> 6;
                const int dd = col & 63;
                {
                    int b_ = r0 >> 12, s = r0 & 4095;
                    float2 st; st.x = acc[mi][nj][0]; st.y = acc[mi][nj][1];
                    *(float2*)(Out + (((size_t)(b_ * HH + h)) * SS + s) * HDIM + dd) = st;
                }
                {
                    int r1 = r0 + 8;
                    int b_ = r1 >> 12, s = r1 & 4095;
                    float2 st; st.x = acc[mi][nj][2]; st.y = acc[mi][nj][3];
                    *(float2*)(Out + (((size_t)(b_ * HH + h)) * SS + s) * HDIM + dd) = st;
                }
            } else {
                float bv0 = bias[n0 + col], bv1 = bias[n0 + col + 1];
                float2 st0; st0.x = acc[mi][nj][0] + bv0; st0.y = acc[mi][nj][1] + bv1;
                float2 st1; st1.x = acc[mi][nj][2] + bv0; st1.y = acc[mi][nj][3] + bv1;
                *(float2*)(out_ptr + (size_t)r0 * DD + n0 + col) = st0;
                *(float2*)(out_ptr + (size_t)(r0 + 8) * DD + n0 + col) = st1;
            }
        }
    }
}

// ---------------------------------------------------------------------------
// BigBird sparse attention, flash-style. 4x4 register micro-tile per thread:
// thread (tr = t>>4, tc = t&15): q-rows tr*4+u, score cols / out dims tc*4+v.
// Row reductions via shfl over the 16-lane tc group.
// Epilogue writes split-bf16 ctx [b,s,h*64+dd] for the HMMA output GEMM.
// ---------------------------------------------------------------------------
#define AST 68   // float stride for Q/K/V/P tiles
#define ATTN_SMEM_BYTES (4 * 64 * AST * 4)

__global__ __launch_bounds__(256) void attn_kernel(
    const float* __restrict__ band_mask,
    const float* __restrict__ from_mask,
    const float* __restrict__ to_mask)
{
    extern __shared__ __align__(16) float sm[];
    float* Qs = sm;                 // 64 x 68
    float* Ks = Qs + 64 * AST;
    float* Vs = Ks + 64 * AST;
    float* Ps = Vs + 64 * AST;

    const int qb = blockIdx.x;
    const int h  = blockIdx.y;
    const int b  = blockIdx.z;
    const int t  = threadIdx.x;
    const int tr = t >> 4;          // 0..15
    const int tc = t & 15;          // 0..15

    const float rs  = 0.125f;
    const float pen = -10000.f;

    // Load Q tile (64x64 -> stride-68 smem)
    {
        const float* qptr = g_q + (((size_t)(b * HH + h)) * SS + qb * BLKSZ) * HDIM;
        for (int i = t; i < 1024; i += 256) {
            int row = i >> 4, c4 = (i & 15) * 4;
            *(float4*)(Qs + row * AST + c4) = *(const float4*)(qptr + row * HDIM + c4);
        }
    }

    // Key-block schedule
    int nt;
    int kbs[5];
    bool is_band;
    if (qb < NGB) {
        nt = NB; is_band = false;
    } else if (qb == NGB) {
        nt = 5; kbs[0]=0; kbs[1]=1; kbs[2]=2; kbs[3]=3; kbs[4]=4; is_band = false;
    } else if (qb == NB - 1) {
        nt = 5; kbs[0]=0; kbs[1]=1; kbs[2]=61; kbs[3]=62; kbs[4]=63; is_band = false;
    } else {
        nt = 5; kbs[0]=0; kbs[1]=1; kbs[2]=qb-1; kbs[3]=qb; kbs[4]=qb+1; is_band = true;
    }

    float m_r[4], l_r[4], accv[4][4];
#pragma unroll
    for (int u = 0; u < 4; u++) {
        m_r[u] = -1e30f; l_r[u] = 0.f;
#pragma unroll
        for (int v = 0; v < 4; v++) accv[u][v] = 0.f;
    }

    const size_t bh_base = ((size_t)(b * HH + h)) * SS;

    for (int it = 0; it < nt; it++) {
        const int kb = (qb < NGB) ? it : kbs[it];

        const float* kptr = g_k + (bh_base + kb * BLKSZ) * HDIM;
        const float* vptr = g_v + (bh_base + kb * BLKSZ) * HDIM;
        for (int i = t; i < 1024; i += 256) {
            int row = i >> 4, c4 = (i & 15) * 4;
            *(float4*)(Ks + row * AST + c4) = *(const float4*)(kptr + row * HDIM + c4);
            *(float4*)(Vs + row * AST + c4) = *(const float4*)(vptr + row * HDIM + c4);
        }
        __syncthreads();

        // Scores: 4x4 micro-tile, float4 over the d dimension
        float p[4][4];
#pragma unroll
        for (int u = 0; u < 4; u++)
#pragma unroll
            for (int v = 0; v < 4; v++) p[u][v] = 0.f;

#pragma unroll 4
        for (int dd4 = 0; dd4 < 16; dd4++) {
            float4 kv[4];
#pragma unroll
            for (int v = 0; v < 4; v++)
                kv[v] = *(const float4*)(Ks + (tc * 4 + v) * AST + dd4 * 4);
#pragma unroll
            for (int u = 0; u < 4; u++) {
                float4 qv = *(const float4*)(Qs + (tr * 4 + u) * AST + dd4 * 4);
#pragma unroll
                for (int v = 0; v < 4; v++) {
                    p[u][v] += qv.x * kv[v].x + qv.y * kv[v].y
                             + qv.z * kv[v].z + qv.w * kv[v].w;
                }
            }
        }

        // Mask + scale
        const bool band_tile = (is_band && it >= 2);
        if (band_tile) {
            const float* bmb = band_mask
                + (((size_t)(b * 60 + (qb - 3)) * 64) * 192) + (size_t)(it - 2) * 64;
#pragma unroll
            for (int u = 0; u < 4; u++) {
                float4 mv = *(const float4*)(bmb + (tr * 4 + u) * 192 + tc * 4);
                p[u][0] = p[u][0] * rs + (1.f - mv.x) * pen;
                p[u][1] = p[u][1] * rs + (1.f - mv.y) * pen;
                p[u][2] = p[u][2] * rs + (1.f - mv.z) * pen;
                p[u][3] = p[u][3] * rs + (1.f - mv.w) * pen;
            }
        } else {
            float4 mv = *(const float4*)(to_mask + (size_t)b * SS + kb * BLKSZ + tc * 4);
#pragma unroll
            for (int u = 0; u < 4; u++) {
                p[u][0] = p[u][0] * rs + (1.f - mv.x) * pen;
                p[u][1] = p[u][1] * rs + (1.f - mv.y) * pen;
                p[u][2] = p[u][2] * rs + (1.f - mv.z) * pen;
                p[u][3] = p[u][3] * rs + (1.f - mv.w) * pen;
            }
        }

        // Streaming softmax per q-row (reduce across tc group = 16 lanes)
#pragma unroll
        for (int u = 0; u < 4; u++) {
            float tm = fmaxf(fmaxf(p[u][0], p[u][1]), fmaxf(p[u][2], p[u][3]));
            tm = fmaxf(tm, __shfl_xor_sync(0xffffffffu, tm, 1));
            tm = fmaxf(tm, __shfl_xor_sync(0xffffffffu, tm, 2));
            tm = fmaxf(tm, __shfl_xor_sync(0xffffffffu, tm, 4));
            tm = fmaxf(tm, __shfl_xor_sync(0xffffffffu, tm, 8));

            float newm = fmaxf(m_r[u], tm);
            float corr = __expf(m_r[u] - newm);
            float4 e;
            e.x = __expf(p[u][0] - newm);
            e.y = __expf(p[u][1] - newm);
            e.z = __expf(p[u][2] - newm);
            e.w = __expf(p[u][3] - newm);
            *(float4*)(Ps + (tr * 4 + u) * AST + tc * 4) = e;
            float ts = e.x + e.y + e.z + e.w;
            ts += __shfl_xor_sync(0xffffffffu, ts, 1);
            ts += __shfl_xor_sync(0xffffffffu, ts, 2);
            ts += __shfl_xor_sync(0xffffffffu, ts, 4);
            ts += __shfl_xor_sync(0xffffffffu, ts, 8);
            l_r[u] = l_r[u] * corr + ts;
            m_r[u] = newm;
#pragma unroll
            for (int v = 0; v < 4; v++) accv[u][v] *= corr;
        }
        __syncwarp();

        // AV: accv[u][v] += sum_c P[row u][c] * V[c][tc*4+v]
#pragma unroll 4
        for (int c = 0; c < 64; c++) {
            float4 vv = *(const float4*)(Vs + c * AST + tc * 4);
            float pv0 = Ps[(tr * 4 + 0) * AST + c];
            float pv1 = Ps[(tr * 4 + 1) * AST + c];
            float pv2 = Ps[(tr * 4 + 2) * AST + c];
            float pv3 = Ps[(tr * 4 + 3) * AST + c];
            accv[0][0] += pv0 * vv.x; accv[0][1] += pv0 * vv.y; accv[0][2] += pv0 * vv.z; accv[0][3] += pv0 * vv.w;
            accv[1][0] += pv1 * vv.x; accv[1][1] += pv1 * vv.y; accv[1][2] += pv1 * vv.z; accv[1][3] += pv1 * vv.w;
            accv[2][0] += pv2 * vv.x; accv[2][1] += pv2 * vv.y; accv[2][2] += pv2 * vv.z; accv[2][3] += pv2 * vv.w;
            accv[3][0] += pv3 * vv.x; accv[3][1] += pv3 * vv.y; accv[3][2] += pv3 * vv.z; accv[3][3] += pv3 * vv.w;
        }
        __syncthreads();
    }

    // Epilogue: split-bf16 ctx[b, s, h*64+dd] * from_mask / l
#pragma unroll
    for (int u = 0; u < 4; u++) {
        const int row = tr * 4 + u;
        const int s   = qb * BLKSZ + row;
        float fm  = from_mask[(size_t)b * SS + s];
        float inv = fm / l_r[u];
        size_t base = ((size_t)b * SS + s) * DD + h * HDIM + tc * 4;
        float vals[4];
#pragma unroll
        for (int v = 0; v < 4; v++) vals[v] = accv[u][v] * inv;
        __nv_bfloat16 hi0 = __float2bfloat16(vals[0]);
        __nv_bfloat16 hi1 = __float2bfloat16(vals[1]);
        __nv_bfloat16 hi2 = __float2bfloat16(vals[2]);
        __nv_bfloat16 hi3 = __float2bfloat16(vals[3]);
        __nv_bfloat162 hA; hA.x = hi0; hA.y = hi1;
        __nv_bfloat162 hB; hB.x = hi2; hB.y = hi3;
        *(__nv_bfloat162*)(g_c_hi + base)     = hA;
        *(__nv_bfloat162*)(g_c_hi + base + 2) = hB;
        __nv_bfloat162 lA, lB;
        lA.x = __float2bfloat16(vals[0] - __bfloat162float(hi0));
        lA.y = __float2bfloat16(vals[1] - __bfloat162float(hi1));
        lB.x = __float2bfloat16(vals[2] - __bfloat162float(hi2));
        lB.y = __float2bfloat16(vals[3] - __bfloat162float(hi3));
        *(__nv_bfloat162*)(g_c_lo + base)     = lA;
        *(__nv_bfloat162*)(g_c_lo + base + 2) = lB;
    }
}

// ---------------------------------------------------------------------------
extern "C" void kernel_launch(void* const* d_in, const int* in_sizes, int n_in,
                              void* d_out, int out_size)
{
    const float* tokens    = (const float*)d_in[0];
    const float* band_mask = (const float*)d_in[1];
    const float* from_mask = (const float*)d_in[2];
    const float* to_mask   = (const float*)d_in[3];
    const float* Wq        = (const float*)d_in[4];
    const float* Wk        = (const float*)d_in[5];
    const float* Wv        = (const float*)d_in[6];
    const float* Wu        = (const float*)d_in[7];
    const float* bu        = (const float*)d_in[8];
    float* out = (float*)d_out;

    cudaFuncSetAttribute(attn_kernel,
                         cudaFuncAttributeMaxDynamicSharedMemorySize, ATTN_SMEM_BYTES);
    cudaFuncSetAttribute(gemm_hmma_kernel,
                         cudaFuncAttributeMaxDynamicSharedMemorySize, GEMM_SMEM_BYTES);

    // 0) Precision-split inputs and weights
    split_x_kernel<<<(MROWS * DD / 4) / 256, 256>>>(tokens);
    wsplit_kernel<<<dim3(1024, 4), 256>>>(Wq, Wk, Wv, Wu);

    // 1) QKV projections (HMMA, grid.z = q/k/v)
    gemm_hmma_kernel<<<dim3(8, 64, 3), 256, GEMM_SMEM_BYTES>>>(0, nullptr, nullptr);

    // 2) Sparse attention (fp32), writes split-bf16 ctx
    attn_kernel<<<dim3(NB, HH, BB), 256, ATTN_SMEM_BYTES>>>(band_mask, from_mask, to_mask);

    // 3) Output projection + bias (HMMA)
    gemm_hmma_kernel<<<dim3(8, 64, 1), 256, GEMM_SMEM_BYTES>>>(3, bu, out);
}

// round 4
// speedup vs baseline: 4.9493x; 1.8081x over previous
#include <cuda_runtime.h>
#include <cuda_bf16.h>
#include <cstdint>
#include <math.h>

#define BB 2
#define SS 4096
#define DD 1024
#define HH 16
#define BLKSZ 64
#define NB 64          // S / BLK
#define NGB 2          // G / BLK
#define HDIM 64        // D / H
#define MROWS (BB*SS)  // 8192

// ---------------------------------------------------------------------------
// Device scratch (no allocation allowed)
// ---------------------------------------------------------------------------
__device__ __nv_bfloat16 g_x_hi[(size_t)MROWS*DD];
__device__ __nv_bfloat16 g_x_lo[(size_t)MROWS*DD];
__device__ __nv_bfloat16 g_c_hi[(size_t)MROWS*DD];
__device__ __nv_bfloat16 g_c_lo[(size_t)MROWS*DD];
__device__ __nv_bfloat16 g_w_hi[(size_t)4*DD*DD];   // [w][k][n] (native layout)
__device__ __nv_bfloat16 g_w_lo[(size_t)4*DD*DD];
// Q/K/V head-split bf16 hi/lo: [b,h,s,64]
__device__ __nv_bfloat16 g_qh[(size_t)BB*HH*SS*HDIM];
__device__ __nv_bfloat16 g_ql[(size_t)BB*HH*SS*HDIM];
__device__ __nv_bfloat16 g_kh[(size_t)BB*HH*SS*HDIM];
__device__ __nv_bfloat16 g_kl[(size_t)BB*HH*SS*HDIM];
__device__ __nv_bfloat16 g_vh[(size_t)BB*HH*SS*HDIM];
__device__ __nv_bfloat16 g_vl[(size_t)BB*HH*SS*HDIM];

// ---------------------------------------------------------------------------
// mma.sync / ldmatrix helpers (generic sm_80+ PTX -- compiles for sm_103)
// ---------------------------------------------------------------------------
__device__ __forceinline__ uint32_t smem_u32(const void* p) {
    uint32_t a;
    asm("{ .reg .u64 t; cvta.to.shared.u64 t, %1; cvt.u32.u64 %0, t; }" : "=r"(a) : "l"(p));
    return a;
}
__device__ __forceinline__ void ldsm_x4(uint32_t* r, uint32_t addr) {
    asm volatile("ldmatrix.sync.aligned.m8n8.x4.shared.b16 {%0,%1,%2,%3}, [%4];"
        : "=r"(r[0]), "=r"(r[1]), "=r"(r[2]), "=r"(r[3]) : "r"(addr));
}
__device__ __forceinline__ void ldsm_x2_trans(uint32_t* r, uint32_t addr) {
    asm volatile("ldmatrix.sync.aligned.m8n8.x2.trans.shared.b16 {%0,%1}, [%2];"
        : "=r"(r[0]), "=r"(r[1]) : "r"(addr));
}
__device__ __forceinline__ void mma_bf16(float (&c)[4], const uint32_t* a,
                                         uint32_t b0, uint32_t b1) {
    asm volatile("mma.sync.aligned.m16n8k16.row.col.f32.bf16.bf16.f32 "
        "{%0,%1,%2,%3}, {%4,%5,%6,%7}, {%8,%9}, {%0,%1,%2,%3};"
        : "+f"(c[0]), "+f"(c[1]), "+f"(c[2]), "+f"(c[3])
        : "r"(a[0]), "r"(a[1]), "r"(a[2]), "r"(a[3]), "r"(b0), "r"(b1));
}
// pack two floats -> bf16x2 hi, bf16x2 lo (residual)
__device__ __forceinline__ uint32_t pack_hilo(float a, float b, uint32_t& lo_out) {
    __nv_bfloat162 h; h.x = __float2bfloat16(a); h.y = __float2bfloat16(b);
    __nv_bfloat162 l;
    l.x = __float2bfloat16(a - __bfloat162float(h.x));
    l.y = __float2bfloat16(b - __bfloat162float(h.y));
    lo_out = *(uint32_t*)&l;
    return *(uint32_t*)&h;
}

// ---------------------------------------------------------------------------
// Split tokens into bf16 hi/lo (row-major [8192, 1024])
// ---------------------------------------------------------------------------
__global__ __launch_bounds__(256) void split_x_kernel(const float* __restrict__ X)
{
    size_t i = (size_t)blockIdx.x * 256 + threadIdx.x;
    float4 v = ((const float4*)X)[i];
    float vs[4] = {v.x, v.y, v.z, v.w};
#pragma unroll
    for (int j = 0; j < 4; j++) {
        __nv_bfloat16 hi = __float2bfloat16(vs[j]);
        float lo = vs[j] - __bfloat162float(hi);
        g_x_hi[i * 4 + j] = hi;
        g_x_lo[i * 4 + j] = __float2bfloat16(lo);
    }
}

// ---------------------------------------------------------------------------
// Elementwise weight split (keeps native [k][n] layout)
// ---------------------------------------------------------------------------
__global__ __launch_bounds__(256) void wsplit_kernel(
    const float* __restrict__ Wq, const float* __restrict__ Wk,
    const float* __restrict__ Wv, const float* __restrict__ Wu)
{
    const int w = blockIdx.y;
    const float* W = (w == 0) ? Wq : (w == 1) ? Wk : (w == 2) ? Wv : Wu;
    size_t i = (size_t)blockIdx.x * 256 + threadIdx.x;
    float4 v = ((const float4*)W)[i];
    float vs[4] = {v.x, v.y, v.z, v.w};
    size_t base = (size_t)w * DD * DD + i * 4;
#pragma unroll
    for (int j = 0; j < 4; j++) {
        __nv_bfloat16 hi = __float2bfloat16(vs[j]);
        float lo = vs[j] - __bfloat162float(hi);
        g_w_hi[base + j] = hi;
        g_w_lo[base + j] = __float2bfloat16(lo);
    }
}

// ---------------------------------------------------------------------------
// Split-bf16 HMMA GEMM: C[8192,1024] = A[8192,1024] @ W[1024,1024]
// mode 0/1/2: out = bf16 hi/lo head-split q/k/v
// mode 3:     out = d_out row-major fp32 + bias
// ---------------------------------------------------------------------------
#define SA_STR 72
#define SB_STR 136
#define SA_HI 0
#define SA_LO (128*SA_STR)
#define SB_HI (2*128*SA_STR)
#define SB_LO (SB_HI + 64*SB_STR)
#define GEMM_SMEM_B16 (SB_LO + 64*SB_STR)
#define GEMM_SMEM_BYTES (GEMM_SMEM_B16 * 2)

__global__ __launch_bounds__(256) void gemm_hmma_kernel(
    int mode_base, const float* __restrict__ bias, float* __restrict__ out_ptr)
{
    extern __shared__ __align__(16) __nv_bfloat16 smem_bf[];
    const uint32_t smem_base = smem_u32(smem_bf);

    const int t    = threadIdx.x;
    const int lane = t & 31;
    const int wid  = t >> 5;
    const int wm   = wid & 3;
    const int wn   = wid >> 2;
    const int mode = mode_base + blockIdx.z;

    const int n0 = blockIdx.x * 128;
    const int m0 = blockIdx.y * 128;

    const __nv_bfloat16* Ahi = (mode < 3) ? g_x_hi : g_c_hi;
    const __nv_bfloat16* Alo = (mode < 3) ? g_x_lo : g_c_lo;
    const __nv_bfloat16* Bhi = g_w_hi + (size_t)mode * DD * DD;
    const __nv_bfloat16* Blo = g_w_lo + (size_t)mode * DD * DD;

    float acc[2][8][4];
#pragma unroll
    for (int mi = 0; mi < 2; mi++)
#pragma unroll
        for (int nj = 0; nj < 8; nj++)
#pragma unroll
            for (int e = 0; e < 4; e++) acc[mi][nj][e] = 0.f;

    const int lrow = lane & 15;
    const int lcol = (lane >> 4) * 8;

    for (int kc = 0; kc < 16; kc++) {
        const int k0 = kc * 64;
#pragma unroll
        for (int it2 = 0; it2 < 4; it2++) {
            int i = t + it2 * 256;
            int row = i >> 3, seg = (i & 7) * 8;
            size_t go = (size_t)(m0 + row) * DD + k0 + seg;
            *(uint4*)(smem_bf + SA_HI + row * SA_STR + seg) = *(const uint4*)(Ahi + go);
            *(uint4*)(smem_bf + SA_LO + row * SA_STR + seg) = *(const uint4*)(Alo + go);
        }
#pragma unroll
        for (int it2 = 0; it2 < 4; it2++) {
            int i = t + it2 * 256;
            int row = i >> 4, seg = (i & 15) * 8;
            size_t go = (size_t)(k0 + row) * DD + n0 + seg;
            *(uint4*)(smem_bf + SB_HI + row * SB_STR + seg) = *(const uint4*)(Bhi + go);
            *(uint4*)(smem_bf + SB_LO + row * SB_STR + seg) = *(const uint4*)(Blo + go);
        }
        __syncthreads();

#pragma unroll
        for (int kk = 0; kk < 4; kk++) {
            const int kb = kk * 16;
            uint32_t ah[2][4], al[2][4];
#pragma unroll
            for (int mi = 0; mi < 2; mi++) {
                uint32_t off = (uint32_t)(((wm * 32 + mi * 16 + lrow) * SA_STR + kb + lcol) * 2);
                ldsm_x4(ah[mi], smem_base + SA_HI * 2 + off);
                ldsm_x4(al[mi], smem_base + SA_LO * 2 + off);
            }
            uint32_t bh[8][2], bl[8][2];
#pragma unroll
            for (int nj = 0; nj < 8; nj++) {
                uint32_t off = (uint32_t)(((kb + lrow) * SB_STR + wn * 64 + nj * 8) * 2);
                ldsm_x2_trans(bh[nj], smem_base + SB_HI * 2 + off);
                ldsm_x2_trans(bl[nj], smem_base + SB_LO * 2 + off);
            }
#pragma unroll
            for (int mi = 0; mi < 2; mi++)
#pragma unroll
                for (int nj = 0; nj < 8; nj++) {
                    mma_bf16(acc[mi][nj], ah[mi], bh[nj][0], bh[nj][1]);
                    mma_bf16(acc[mi][nj], ah[mi], bl[nj][0], bl[nj][1]);
                    mma_bf16(acc[mi][nj], al[mi], bh[nj][0], bh[nj][1]);
                }
        }
        __syncthreads();
    }

    // Epilogue
#pragma unroll
    for (int mi = 0; mi < 2; mi++) {
        const int r0 = m0 + wm * 32 + mi * 16 + (lane >> 2);
#pragma unroll
        for (int nj = 0; nj < 8; nj++) {
            const int col = wn * 64 + nj * 8 + (lane & 3) * 2;
            if (mode < 3) {
                __nv_bfloat16* Oh = (mode == 0) ? g_qh : (mode == 1) ? g_kh : g_vh;
                __nv_bfloat16* Ol = (mode == 0) ? g_ql : (mode == 1) ? g_kl : g_vl;
                const int h  = (n0 + col) >> 6;
                const int dd = col & 63;
#pragma unroll
                for (int half = 0; half < 2; half++) {
                    int r = r0 + half * 8;
                    int b_ = r >> 12, s = r & 4095;
                    float a0 = acc[mi][nj][half * 2 + 0];
                    float a1 = acc[mi][nj][half * 2 + 1];
                    uint32_t lo, hi = pack_hilo(a0, a1, lo);
                    size_t idx = (((size_t)(b_ * HH + h)) * SS + s) * HDIM + dd;
                    *(uint32_t*)(Oh + idx) = hi;
                    *(uint32_t*)(Ol + idx) = lo;
                }
            } else {
                float bv0 = bias[n0 + col], bv1 = bias[n0 + col + 1];
                float2 st0; st0.x = acc[mi][nj][0] + bv0; st0.y = acc[mi][nj][1] + bv1;
                float2 st1; st1.x = acc[mi][nj][2] + bv0; st1.y = acc[mi][nj][3] + bv1;
                *(float2*)(out_ptr + (size_t)r0 * DD + n0 + col) = st0;
                *(float2*)(out_ptr + (size_t)(r0 + 8) * DD + n0 + col) = st1;
            }
        }
    }
}

// ---------------------------------------------------------------------------
// BigBird sparse attention on HMMA, flash-style streaming softmax.
// 128 threads / 4 warps; warp w owns q rows w*16..w*16+15.
// Scores: 3 split products (qh*kh + qh*kl + ql*kh) -> fp32 frags.
// P packed bf16 hi/lo directly from C-frag layout into A-frag layout.
// PV: 3 split products (Ph*Vh + Ph*Vl + Pl*Vh).
// ---------------------------------------------------------------------------
#define ATT_STR 72                       // b16 stride
#define A_QH 0
#define A_QL (64*ATT_STR)
#define A_KH (2*64*ATT_STR)
#define A_KL (3*64*ATT_STR)
#define A_VH (4*64*ATT_STR)
#define A_VL (5*64*ATT_STR)
#define A_B16_TOTAL (6*64*ATT_STR)       // 27648 b16 = 55296 B
#define PEN2_OFF (A_B16_TOTAL*2)         // byte offset of pen2d
#define PEN2_STR 68
#define PEN1_OFF (PEN2_OFF + 64*PEN2_STR*4)
#define ATTN_SMEM_BYTES (PEN1_OFF + 64*4)

__global__ __launch_bounds__(128) void attn_kernel(
    const float* __restrict__ band_mask,
    const float* __restrict__ from_mask,
    const float* __restrict__ to_mask)
{
    extern __shared__ __align__(16) char smraw[];
    __nv_bfloat16* sb = (__nv_bfloat16*)smraw;
    float* pen2d = (float*)(smraw + PEN2_OFF);
    float* pen1  = (float*)(smraw + PEN1_OFF);
    const uint32_t smem_base = smem_u32(smraw);

    const int qb = blockIdx.x;
    const int h  = blockIdx.y;
    const int b  = blockIdx.z;
    const int t  = threadIdx.x;
    const int lane = t & 31;
    const int wid  = t >> 5;

    const float rs  = 0.125f;
    const float pen = -10000.f;

    const size_t bh64 = ((size_t)(b * HH + h)) * SS * HDIM;

    // ---- Load Q tile (hi/lo) and build per-warp A-fragments ----
    {
        const __nv_bfloat16* qhp = g_qh + bh64 + (size_t)qb * BLKSZ * HDIM;
        const __nv_bfloat16* qlp = g_ql + bh64 + (size_t)qb * BLKSZ * HDIM;
        for (int i = t; i < 512; i += 128) {
            int row = i >> 3, seg = (i & 7) * 8;
            *(uint4*)(sb + A_QH + row * ATT_STR + seg) = *(const uint4*)(qhp + row * HDIM + seg);
            *(uint4*)(sb + A_QL + row * ATT_STR + seg) = *(const uint4*)(qlp + row * HDIM + seg);
        }
    }
    __syncthreads();

    uint32_t qfh[4][4], qfl[4][4];
    {
        const int lrow = lane & 15;
        const int lcol = (lane >> 4) * 8;
#pragma unroll
        for (int kk = 0; kk < 4; kk++) {
            uint32_t off = (uint32_t)(((wid * 16 + lrow) * ATT_STR + kk * 16 + lcol) * 2);
            ldsm_x4(qfh[kk], smem_base + A_QH * 2 + off);
            ldsm_x4(qfl[kk], smem_base + A_QL * 2 + off);
        }
    }

    // ---- Key-block schedule ----
    int nt;
    int kbs[5];
    bool is_band;
    if (qb < NGB) {
        nt = NB; is_band = false;
    } else if (qb == NGB) {
        nt = 5; kbs[0]=0; kbs[1]=1; kbs[2]=2; kbs[3]=3; kbs[4]=4; is_band = false;
    } else if (qb == NB - 1) {
        nt = 5; kbs[0]=0; kbs[1]=1; kbs[2]=61; kbs[3]=62; kbs[4]=63; is_band = false;
    } else {
        nt = 5; kbs[0]=0; kbs[1]=1; kbs[2]=qb-1; kbs[3]=qb; kbs[4]=qb+1; is_band = true;
    }

    // ---- flash state ----
    float m0 = -1e30f, m1 = -1e30f, l0 = 0.f, l1 = 0.f;
    float o[8][4];
#pragma unroll
    for (int nj = 0; nj < 8; nj++)
#pragma unroll
        for (int e = 0; e < 4; e++) o[nj][e] = 0.f;

    for (int it = 0; it < nt; it++) {
        const int kb = (qb < NGB) ? it : kbs[it];
        const bool band_tile = (is_band && it >= 2);

        // ---- Fill K/V hi/lo tiles ----
        {
            const __nv_bfloat16* khp = g_kh + bh64 + (size_t)kb * BLKSZ * HDIM;
            const __nv_bfloat16* klp = g_kl + bh64 + (size_t)kb * BLKSZ * HDIM;
            const __nv_bfloat16* vhp = g_vh + bh64 + (size_t)kb * BLKSZ * HDIM;
            const __nv_bfloat16* vlp = g_vl + bh64 + (size_t)kb * BLKSZ * HDIM;
            for (int i = t; i < 512; i += 128) {
                int row = i >> 3, seg = (i & 7) * 8;
                int so = row * ATT_STR + seg, go = row * HDIM + seg;
                *(uint4*)(sb + A_KH + so) = *(const uint4*)(khp + go);
                *(uint4*)(sb + A_KL + so) = *(const uint4*)(klp + go);
                *(uint4*)(sb + A_VH + so) = *(const uint4*)(vhp + go);
                *(uint4*)(sb + A_VL + so) = *(const uint4*)(vlp + go);
            }
        }
        // ---- Fill penalty tiles ----
        if (band_tile) {
            const float* bmb = band_mask
                + ((size_t)(b * 60 + (qb - 3)) * 64) * 192 + (size_t)(it - 2) * 64;
            for (int i = t; i < 1024; i += 128) {
                int row = i >> 4, c4 = (i & 15) * 4;
                float4 mv = *(const float4*)(bmb + row * 192 + c4);
                float* d = pen2d + row * PEN2_STR + c4;
                d[0] = (1.f - mv.x) * pen; d[1] = (1.f - mv.y) * pen;
                d[2] = (1.f - mv.z) * pen; d[3] = (1.f - mv.w) * pen;
            }
        } else {
            if (t < 16) {
                float4 mv = *(const float4*)(to_mask + (size_t)b * SS + kb * BLKSZ + t * 4);
                pen1[t*4+0] = (1.f - mv.x) * pen; pen1[t*4+1] = (1.f - mv.y) * pen;
                pen1[t*4+2] = (1.f - mv.z) * pen; pen1[t*4+3] = (1.f - mv.w) * pen;
            }
        }
        __syncthreads();

        // ---- Scores: S = Q K^T (split precision) ----
        float acc[8][4];
#pragma unroll
        for (int nj = 0; nj < 8; nj++)
#pragma unroll
            for (int e = 0; e < 4; e++) acc[nj][e] = 0.f;

#pragma unroll
        for (int nj = 0; nj < 8; nj++) {
            uint32_t kh8[8], kl8[8];
            uint32_t rbase = (uint32_t)(((nj * 8 + (lane & 7)) * ATT_STR + (lane >> 3) * 8) * 2);
            ldsm_x4(kh8,     smem_base + A_KH * 2 + rbase);
            ldsm_x4(kh8 + 4, smem_base + A_KH * 2 + rbase + 64);   // +32 cols * 2B
            ldsm_x4(kl8,     smem_base + A_KL * 2 + rbase);
            ldsm_x4(kl8 + 4, smem_base + A_KL * 2 + rbase + 64);
#pragma unroll
            for (int kk = 0; kk < 4; kk++) {
                mma_bf16(acc[nj], qfh[kk], kh8[2*kk], kh8[2*kk+1]);
                mma_bf16(acc[nj], qfh[kk], kl8[2*kk], kl8[2*kk+1]);
                mma_bf16(acc[nj], qfl[kk], kh8[2*kk], kh8[2*kk+1]);
            }
        }

        // ---- Scale + mask ----
        const int qr0 = wid * 16 + (lane >> 2);
#pragma unroll
        for (int nj = 0; nj < 8; nj++) {
#pragma unroll
            for (int e = 0; e < 4; e++) {
                int col = nj * 8 + (lane & 3) * 2 + (e & 1);
                float pe = band_tile
                    ? pen2d[(qr0 + (e >> 1) * 8) * PEN2_STR + col]
                    : pen1[col];
                acc[nj][e] = acc[nj][e] * rs + pe;
            }
        }

        // ---- Streaming softmax ----
        float tm0 = -1e30f, tm1 = -1e30f;
#pragma unroll
        for (int nj = 0; nj < 8; nj++) {
            tm0 = fmaxf(tm0, fmaxf(acc[nj][0], acc[nj][1]));
            tm1 = fmaxf(tm1, fmaxf(acc[nj][2], acc[nj][3]));
        }
        tm0 = fmaxf(tm0, __shfl_xor_sync(0xffffffffu, tm0, 1));
        tm0 = fmaxf(tm0, __shfl_xor_sync(0xffffffffu, tm0, 2));
        tm1 = fmaxf(tm1, __shfl_xor_sync(0xffffffffu, tm1, 1));
        tm1 = fmaxf(tm1, __shfl_xor_sync(0xffffffffu, tm1, 2));

        float nm0 = fmaxf(m0, tm0), nm1 = fmaxf(m1, tm1);
        float c0 = __expf(m0 - nm0), c1 = __expf(m1 - nm1);
        float ts0 = 0.f, ts1 = 0.f;
#pragma unroll
        for (int nj = 0; nj < 8; nj++) {
            acc[nj][0] = __expf(acc[nj][0] - nm0);
            acc[nj][1] = __expf(acc[nj][1] - nm0);
            acc[nj][2] = __expf(acc[nj][2] - nm1);
            acc[nj][3] = __expf(acc[nj][3] - nm1);
            ts0 += acc[nj][0] + acc[nj][1];
            ts1 += acc[nj][2] + acc[nj][3];
        }
        ts0 += __shfl_xor_sync(0xffffffffu, ts0, 1);
        ts0 += __shfl_xor_sync(0xffffffffu, ts0, 2);
        ts1 += __shfl_xor_sync(0xffffffffu, ts1, 1);
        ts1 += __shfl_xor_sync(0xffffffffu, ts1, 2);
        l0 = l0 * c0 + ts0;  l1 = l1 * c1 + ts1;
        m0 = nm0;  m1 = nm1;
#pragma unroll
        for (int nj = 0; nj < 8; nj++) {
            o[nj][0] *= c0; o[nj][1] *= c0;
            o[nj][2] *= c1; o[nj][3] *= c1;
        }

        // ---- Pack P -> A-frags (bf16 hi/lo), C-frag layout == A-frag layout ----
        uint32_t phi[4][4], plo[4][4];
#pragma unroll
        for (int kk2 = 0; kk2 < 4; kk2++) {
            phi[kk2][0] = pack_hilo(acc[2*kk2][0],   acc[2*kk2][1],   plo[kk2][0]);
            phi[kk2][1] = pack_hilo(acc[2*kk2][2],   acc[2*kk2][3],   plo[kk2][1]);
            phi[kk2][2] = pack_hilo(acc[2*kk2+1][0], acc[2*kk2+1][1], plo[kk2][2]);
            phi[kk2][3] = pack_hilo(acc[2*kk2+1][2], acc[2*kk2+1][3], plo[kk2][3]);
        }

        // ---- PV: O += P V (split precision) ----
#pragma unroll
        for (int njd = 0; njd < 8; njd++) {
#pragma unroll
            for (int kk2 = 0; kk2 < 4; kk2++) {
                uint32_t vh[2], vl[2];
                uint32_t off = (uint32_t)(((kk2 * 16 + (lane & 15)) * ATT_STR + njd * 8) * 2);
                ldsm_x2_trans(vh, smem_base + A_VH * 2 + off);
                ldsm_x2_trans(vl, smem_base + A_VL * 2 + off);
                mma_bf16(o[njd], phi[kk2], vh[0], vh[1]);
                mma_bf16(o[njd], phi[kk2], vl[0], vl[1]);
                mma_bf16(o[njd], plo[kk2], vh[0], vh[1]);
            }
        }
        __syncthreads();
    }

    // ---- Epilogue: ctx = O * from_mask / l, split bf16 hi/lo ----
    const int r0 = wid * 16 + (lane >> 2);
    const int s0 = qb * BLKSZ + r0;
    const int s1 = s0 + 8;
    float inv0 = from_mask[(size_t)b * SS + s0] / l0;
    float inv1 = from_mask[(size_t)b * SS + s1] / l1;
#pragma unroll
    for (int njd = 0; njd < 8; njd++) {
        const int col = njd * 8 + (lane & 3) * 2;
        {
            size_t idx = ((size_t)b * SS + s0) * DD + h * HDIM + col;
            uint32_t lo, hi = pack_hilo(o[njd][0] * inv0, o[njd][1] * inv0, lo);
            *(uint32_t*)(g_c_hi + idx) = hi;
            *(uint32_t*)(g_c_lo + idx) = lo;
        }
        {
            size_t idx = ((size_t)b * SS + s1) * DD + h * HDIM + col;
            uint32_t lo, hi = pack_hilo(o[njd][2] * inv1, o[njd][3] * inv1, lo);
            *(uint32_t*)(g_c_hi + idx) = hi;
            *(uint32_t*)(g_c_lo + idx) = lo;
        }
    }
}

// ---------------------------------------------------------------------------
extern "C" void kernel_launch(void* const* d_in, const int* in_sizes, int n_in,
                              void* d_out, int out_size)
{
    const float* tokens    = (const float*)d_in[0];
    const float* band_mask = (const float*)d_in[1];
    const float* from_mask = (const float*)d_in[2];
    const float* to_mask   = (const float*)d_in[3];
    const float* Wq        = (const float*)d_in[4];
    const float* Wk        = (const float*)d_in[5];
    const float* Wv        = (const float*)d_in[6];
    const float* Wu        = (const float*)d_in[7];
    const float* bu        = (const float*)d_in[8];
    float* out = (float*)d_out;

    cudaFuncSetAttribute(attn_kernel,
                         cudaFuncAttributeMaxDynamicSharedMemorySize, ATTN_SMEM_BYTES);
    cudaFuncSetAttribute(gemm_hmma_kernel,
                         cudaFuncAttributeMaxDynamicSharedMemorySize, GEMM_SMEM_BYTES);

    // 0) Precision-split inputs and weights
    split_x_kernel<<<(MROWS * DD / 4) / 256, 256>>>(tokens);
    wsplit_kernel<<<dim3(1024, 4), 256>>>(Wq, Wk, Wv, Wu);

    // 1) QKV projections (HMMA, grid.z = q/k/v), bf16 hi/lo epilogue
    gemm_hmma_kernel<<<dim3(8, 64, 3), 256, GEMM_SMEM_BYTES>>>(0, nullptr, nullptr);

    // 2) Sparse attention on HMMA, writes split-bf16 ctx
    attn_kernel<<<dim3(NB, HH, BB), 128, ATTN_SMEM_BYTES>>>(band_mask, from_mask, to_mask);

    // 3) Output projection + bias (HMMA)
    gemm_hmma_kernel<<<dim3(8, 64, 1), 256, GEMM_SMEM_BYTES>>>(3, bu, out);
}

// round 5
// speedup vs baseline: 6.8949x; 1.3931x over previous
#include <cuda_runtime.h>
#include <cuda_bf16.h>
#include <cstdint>
#include <math.h>

#define BB 2
#define SS 4096
#define DD 1024
#define HH 16
#define BLKSZ 64
#define NB 64          // S / BLK
#define NGB 2          // G / BLK
#define HDIM 64        // D / H
#define MROWS (BB*SS)  // 8192

// ---------------------------------------------------------------------------
// Device scratch (no allocation allowed)
// ---------------------------------------------------------------------------
__device__ __nv_bfloat16 g_x_hi[(size_t)MROWS*DD];
__device__ __nv_bfloat16 g_x_lo[(size_t)MROWS*DD];
__device__ __nv_bfloat16 g_c_hi[(size_t)MROWS*DD];
__device__ __nv_bfloat16 g_c_lo[(size_t)MROWS*DD];
__device__ __nv_bfloat16 g_w_hi[(size_t)4*DD*DD];   // [w][k][n] (native layout)
__device__ __nv_bfloat16 g_w_lo[(size_t)4*DD*DD];
// Q/K/V head-split bf16 hi/lo: [b,h,s,64]
__device__ __nv_bfloat16 g_qh[(size_t)BB*HH*SS*HDIM];
__device__ __nv_bfloat16 g_ql[(size_t)BB*HH*SS*HDIM];
__device__ __nv_bfloat16 g_kh[(size_t)BB*HH*SS*HDIM];
__device__ __nv_bfloat16 g_kl[(size_t)BB*HH*SS*HDIM];
__device__ __nv_bfloat16 g_vh[(size_t)BB*HH*SS*HDIM];
__device__ __nv_bfloat16 g_vl[(size_t)BB*HH*SS*HDIM];
// split-KV partials for heavy q-blocks: 512 chunks x (64x64 O + 64 m + 64 l)
__device__ float g_po[(size_t)512*4096];
__device__ float g_pm[512*64];
__device__ float g_pl[512*64];

// ---------------------------------------------------------------------------
// mma.sync / ldmatrix / cp.async helpers (generic sm_80+ PTX)
// ---------------------------------------------------------------------------
__device__ __forceinline__ uint32_t smem_u32(const void* p) {
    uint32_t a;
    asm("{ .reg .u64 t; cvta.to.shared.u64 t, %1; cvt.u32.u64 %0, t; }" : "=r"(a) : "l"(p));
    return a;
}
__device__ __forceinline__ void ldsm_x4(uint32_t* r, uint32_t addr) {
    asm volatile("ldmatrix.sync.aligned.m8n8.x4.shared.b16 {%0,%1,%2,%3}, [%4];"
        : "=r"(r[0]), "=r"(r[1]), "=r"(r[2]), "=r"(r[3]) : "r"(addr));
}
__device__ __forceinline__ void ldsm_x2_trans(uint32_t* r, uint32_t addr) {
    asm volatile("ldmatrix.sync.aligned.m8n8.x2.trans.shared.b16 {%0,%1}, [%2];"
        : "=r"(r[0]), "=r"(r[1]) : "r"(addr));
}
__device__ __forceinline__ void mma_bf16(float (&c)[4], const uint32_t* a,
                                         uint32_t b0, uint32_t b1) {
    asm volatile("mma.sync.aligned.m16n8k16.row.col.f32.bf16.bf16.f32 "
        "{%0,%1,%2,%3}, {%4,%5,%6,%7}, {%8,%9}, {%0,%1,%2,%3};"
        : "+f"(c[0]), "+f"(c[1]), "+f"(c[2]), "+f"(c[3])
        : "r"(a[0]), "r"(a[1]), "r"(a[2]), "r"(a[3]), "r"(b0), "r"(b1));
}
__device__ __forceinline__ void cp_async16(uint32_t saddr, const void* gptr) {
    asm volatile("cp.async.cg.shared.global [%0], [%1], 16;" :: "r"(saddr), "l"(gptr));
}
#define CP_COMMIT asm volatile("cp.async.commit_group;")
#define CP_WAIT1  asm volatile("cp.async.wait_group 1;")
#define CP_WAIT0  asm volatile("cp.async.wait_group 0;")

// pack two floats -> bf16x2 hi, bf16x2 lo (residual)
__device__ __forceinline__ uint32_t pack_hilo(float a, float b, uint32_t& lo_out) {
    __nv_bfloat162 h; h.x = __float2bfloat16(a); h.y = __float2bfloat16(b);
    __nv_bfloat162 l;
    l.x = __float2bfloat16(a - __bfloat162float(h.x));
    l.y = __float2bfloat16(b - __bfloat162float(h.y));
    lo_out = *(uint32_t*)&l;
    return *(uint32_t*)&h;
}

// ---------------------------------------------------------------------------
// Split tokens into bf16 hi/lo (row-major [8192, 1024])
// ---------------------------------------------------------------------------
__global__ __launch_bounds__(256) void split_x_kernel(const float* __restrict__ X)
{
    size_t i = (size_t)blockIdx.x * 256 + threadIdx.x;
    float4 v = ((const float4*)X)[i];
    float vs[4] = {v.x, v.y, v.z, v.w};
#pragma unroll
    for (int j = 0; j < 4; j++) {
        __nv_bfloat16 hi = __float2bfloat16(vs[j]);
        float lo = vs[j] - __bfloat162float(hi);
        g_x_hi[i * 4 + j] = hi;
        g_x_lo[i * 4 + j] = __float2bfloat16(lo);
    }
}

// ---------------------------------------------------------------------------
// Elementwise weight split (keeps native [k][n] layout)
// ---------------------------------------------------------------------------
__global__ __launch_bounds__(256) void wsplit_kernel(
    const float* __restrict__ Wq, const float* __restrict__ Wk,
    const float* __restrict__ Wv, const float* __restrict__ Wu)
{
    const int w = blockIdx.y;
    const float* W = (w == 0) ? Wq : (w == 1) ? Wk : (w == 2) ? Wv : Wu;
    size_t i = (size_t)blockIdx.x * 256 + threadIdx.x;
    float4 v = ((const float4*)W)[i];
    float vs[4] = {v.x, v.y, v.z, v.w};
    size_t base = (size_t)w * DD * DD + i * 4;
#pragma unroll
    for (int j = 0; j < 4; j++) {
        __nv_bfloat16 hi = __float2bfloat16(vs[j]);
        float lo = vs[j] - __bfloat162float(hi);
        g_w_hi[base + j] = hi;
        g_w_lo[base + j] = __float2bfloat16(lo);
    }
}

// ---------------------------------------------------------------------------
// Split-bf16 HMMA GEMM with cp.async double buffering.
// CTA 128x128, K-chunk 32, 2 stages. 8 warps: wm=wid&3, wn=wid>>2.
// mode 0/1/2: out = bf16 hi/lo head-split q/k/v;  mode 3: fp32 out + bias.
// ---------------------------------------------------------------------------
#define GK 32
#define SA2 40            // A stride (b16): 32 + 8 pad
#define SB2 136           // B stride (b16)
#define SA_HI_B 0         // byte offsets within a stage
#define SA_LO_B 10240     // 128*40*2
#define SB_HI_B 20480
#define SB_LO_B 29184     // +32*136*2
#define STAGE_B 37888
#define GEMM_SMEM_BYTES (2*STAGE_B)

__global__ __launch_bounds__(256, 2) void gemm_hmma_kernel(
    int mode_base, const float* __restrict__ bias, float* __restrict__ out_ptr)
{
    extern __shared__ __align__(16) char gsm[];
    const uint32_t smem_base = smem_u32(gsm);

    const int t    = threadIdx.x;
    const int lane = t & 31;
    const int wid  = t >> 5;
    const int wm   = wid & 3;
    const int wn   = wid >> 2;
    const int mode = mode_base + blockIdx.z;

    const int n0 = blockIdx.x * 128;
    const int m0 = blockIdx.y * 128;

    const __nv_bfloat16* Ahi = (mode < 3) ? g_x_hi : g_c_hi;
    const __nv_bfloat16* Alo = (mode < 3) ? g_x_lo : g_c_lo;
    const __nv_bfloat16* Bhi = g_w_hi + (size_t)mode * DD * DD;
    const __nv_bfloat16* Blo = g_w_lo + (size_t)mode * DD * DD;

    float acc[2][8][4];
#pragma unroll
    for (int mi = 0; mi < 2; mi++)
#pragma unroll
        for (int nj = 0; nj < 8; nj++)
#pragma unroll
            for (int e = 0; e < 4; e++) acc[mi][nj][e] = 0.f;

    const int lrow = lane & 15;
    const int lcol = (lane >> 4) * 8;

    // A fill: i = t, t+256 -> row=i>>2 (0..127), seg=(i&3)*8
    // B fill: i = t, t+256 -> row=i>>4 (0..31),  seg=(i&15)*8
    const int arow0 = t >> 2,          aseg0 = (t & 3) * 8;
    const int arow1 = (t + 256) >> 2,  aseg1 = ((t + 256) & 3) * 8;
    const int brow0 = t >> 4,          bseg0 = (t & 15) * 8;
    const int brow1 = (t + 256) >> 4,  bseg1 = ((t + 256) & 15) * 8;

#define GEMM_PREFETCH(KC) do {                                              \
    const int k0_ = (KC) * GK;                                              \
    const uint32_t sb_ = smem_base + ((KC) & 1) * STAGE_B;                  \
    {   size_t go = (size_t)(m0 + arow0) * DD + k0_ + aseg0;                \
        uint32_t so = sb_ + (uint32_t)(arow0 * SA2 + aseg0) * 2;            \
        cp_async16(so + SA_HI_B, Ahi + go);                                 \
        cp_async16(so + SA_LO_B, Alo + go); }                               \
    {   size_t go = (size_t)(m0 + arow1) * DD + k0_ + aseg1;                \
        uint32_t so = sb_ + (uint32_t)(arow1 * SA2 + aseg1) * 2;            \
        cp_async16(so + SA_HI_B, Ahi + go);                                 \
        cp_async16(so + SA_LO_B, Alo + go); }                               \
    {   size_t go = (size_t)(k0_ + brow0) * DD + n0 + bseg0;                \
        uint32_t so = sb_ + (uint32_t)(brow0 * SB2 + bseg0) * 2;            \
        cp_async16(so + SB_HI_B, Bhi + go);                                 \
        cp_async16(so + SB_LO_B, Blo + go); }                               \
    {   size_t go = (size_t)(k0_ + brow1) * DD + n0 + bseg1;                \
        uint32_t so = sb_ + (uint32_t)(brow1 * SB2 + bseg1) * 2;            \
        cp_async16(so + SB_HI_B, Bhi + go);                                 \
        cp_async16(so + SB_LO_B, Blo + go); }                               \
    CP_COMMIT; } while (0)

    GEMM_PREFETCH(0);

    for (int kc = 0; kc < 32; kc++) {
        if (kc + 1 < 32) { GEMM_PREFETCH(kc + 1); CP_WAIT1; }
        else             { CP_WAIT0; }
        __syncthreads();

        const uint32_t sb = smem_base + (kc & 1) * STAGE_B;
#pragma unroll
        for (int kk = 0; kk < 2; kk++) {
            uint32_t ah[2][4], al[2][4];
#pragma unroll
            for (int mi = 0; mi < 2; mi++) {
                uint32_t off = (uint32_t)((wm * 32 + mi * 16 + lrow) * SA2 + kk * 16 + lcol) * 2;
                ldsm_x4(ah[mi], sb + SA_HI_B + off);
                ldsm_x4(al[mi], sb + SA_LO_B + off);
            }
            uint32_t bh[8][2], bl[8][2];
#pragma unroll
            for (int nj = 0; nj < 8; nj++) {
                uint32_t off = (uint32_t)((kk * 16 + lrow) * SB2 + wn * 64 + nj * 8) * 2;
                ldsm_x2_trans(bh[nj], sb + SB_HI_B + off);
                ldsm_x2_trans(bl[nj], sb + SB_LO_B + off);
            }
#pragma unroll
            for (int mi = 0; mi < 2; mi++)
#pragma unroll
                for (int nj = 0; nj < 8; nj++) {
                    mma_bf16(acc[mi][nj], ah[mi], bh[nj][0], bh[nj][1]);
                    mma_bf16(acc[mi][nj], ah[mi], bl[nj][0], bl[nj][1]);
                    mma_bf16(acc[mi][nj], al[mi], bh[nj][0], bh[nj][1]);
                }
        }
        __syncthreads();
    }

    // Epilogue
#pragma unroll
    for (int mi = 0; mi < 2; mi++) {
        const int r0 = m0 + wm * 32 + mi * 16 + (lane >> 2);
#pragma unroll
        for (int nj = 0; nj < 8; nj++) {
            const int col = wn * 64 + nj * 8 + (lane & 3) * 2;
            if (mode < 3) {
                __nv_bfloat16* Oh = (mode == 0) ? g_qh : (mode == 1) ? g_kh : g_vh;
                __nv_bfloat16* Ol = (mode == 0) ? g_ql : (mode == 1) ? g_kl : g_vl;
                const int h  = (n0 + col) >> 6;
                const int dd = col & 63;
#pragma unroll
                for (int half = 0; half < 2; half++) {
                    int r = r0 + half * 8;
                    int b_ = r >> 12, s = r & 4095;
                    float a0 = acc[mi][nj][half * 2 + 0];
                    float a1 = acc[mi][nj][half * 2 + 1];
                    uint32_t lo, hi = pack_hilo(a0, a1, lo);
                    size_t idx = (((size_t)(b_ * HH + h)) * SS + s) * HDIM + dd;
                    *(uint32_t*)(Oh + idx) = hi;
                    *(uint32_t*)(Ol + idx) = lo;
                }
            } else {
                float bv0 = bias[n0 + col], bv1 = bias[n0 + col + 1];
                float2 st0; st0.x = acc[mi][nj][0] + bv0; st0.y = acc[mi][nj][1] + bv1;
                float2 st1; st1.x = acc[mi][nj][2] + bv0; st1.y = acc[mi][nj][3] + bv1;
                *(float2*)(out_ptr + (size_t)r0 * DD + n0 + col) = st0;
                *(float2*)(out_ptr + (size_t)(r0 + 8) * DD + n0 + col) = st1;
            }
        }
    }
}

// ---------------------------------------------------------------------------
// BigBird sparse attention on HMMA + split-KV for heavy q-blocks.
// grid.x = 78: bx<62 -> light (qb = bx+2, 5 tiles);  bx>=62 -> heavy
// (qb = (bx-62)>>3 in {0,1}, chunk = (bx-62)&7, 8 key tiles, writes partials).
// pen2d overlays the Q staging area (Q only needed for one-time frag load).
// ---------------------------------------------------------------------------
#define ATT_STRB 144                  // 72 b16 row stride, in bytes
#define T_KH 0
#define T_KL 9216
#define T_VH 18432
#define T_VL 27648
#define T_QH 36864
#define T_QL 46080
#define T_PEN2 36864                  // float[64][68], overlays Q area
#define T_PEN1 55296                  // float[64]
#define ATTN_SMEM_BYTES 55552

__global__ __launch_bounds__(128, 3) void attn_kernel(
    const float* __restrict__ band_mask,
    const float* __restrict__ from_mask,
    const float* __restrict__ to_mask)
{
    extern __shared__ __align__(16) char smraw[];
    const uint32_t smem_base = smem_u32(smraw);
    float* pen2d = (float*)(smraw + T_PEN2);
    float* pen1  = (float*)(smraw + T_PEN1);

    const int bx = blockIdx.x;
    const int h  = blockIdx.y;
    const int b  = blockIdx.z;
    const int t  = threadIdx.x;
    const int lane = t & 31;
    const int wid  = t >> 5;

    const bool heavy = (bx >= 62);
    int qb, ch = 0;
    if (heavy) { int hx = bx - 62; qb = hx >> 3; ch = hx & 7; }
    else qb = bx + 2;

    const float rs  = 0.125f;
    const float pen = -10000.f;
    const size_t bh64 = ((size_t)(b * HH + h)) * SS * HDIM;

    // ---- Load Q tile (hi/lo) into staging area ----
    {
        const __nv_bfloat16* qhp = g_qh + bh64 + (size_t)qb * BLKSZ * HDIM;
        const __nv_bfloat16* qlp = g_ql + bh64 + (size_t)qb * BLKSZ * HDIM;
        for (int i = t; i < 512; i += 128) {
            int row = i >> 3, seg = (i & 7) * 8;
            *(uint4*)(smraw + T_QH + row * ATT_STRB + seg * 2) = *(const uint4*)(qhp + row * HDIM + seg);
            *(uint4*)(smraw + T_QL + row * ATT_STRB + seg * 2) = *(const uint4*)(qlp + row * HDIM + seg);
        }
    }
    __syncthreads();

    uint32_t qfh[4][4], qfl[4][4];
    {
        const int lrow = lane & 15;
        const int lcol = (lane >> 4) * 8;
#pragma unroll
        for (int kk = 0; kk < 4; kk++) {
            uint32_t off = (uint32_t)((wid * 16 + lrow) * ATT_STRB + (kk * 16 + lcol) * 2);
            ldsm_x4(qfh[kk], smem_base + T_QH + off);
            ldsm_x4(qfl[kk], smem_base + T_QL + off);
        }
    }
    __syncthreads();   // everyone done reading Q before pen2d overlays it

    // ---- schedule ----
    int nt;
    int kbs[5];
    bool is_band = false;
    if (heavy) {
        nt = 8;
    } else if (qb == NGB) {
        nt = 5; kbs[0]=0; kbs[1]=1; kbs[2]=2; kbs[3]=3; kbs[4]=4;
    } else if (qb == NB - 1) {
        nt = 5; kbs[0]=0; kbs[1]=1; kbs[2]=61; kbs[3]=62; kbs[4]=63;
    } else {
        nt = 5; kbs[0]=0; kbs[1]=1; kbs[2]=qb-1; kbs[3]=qb; kbs[4]=qb+1; is_band = true;
    }

    float m0 = -1e30f, m1 = -1e30f, l0 = 0.f, l1 = 0.f;
    float o[8][4];
#pragma unroll
    for (int nj = 0; nj < 8; nj++)
#pragma unroll
        for (int e = 0; e < 4; e++) o[nj][e] = 0.f;

    for (int it = 0; it < nt; it++) {
        const int kb = heavy ? (ch * 8 + it) : kbs[it];
        const bool band_tile = (is_band && it >= 2);

        // ---- Fill K/V hi/lo tiles ----
        {
            const __nv_bfloat16* khp = g_kh + bh64 + (size_t)kb * BLKSZ * HDIM;
            const __nv_bfloat16* klp = g_kl + bh64 + (size_t)kb * BLKSZ * HDIM;
            const __nv_bfloat16* vhp = g_vh + bh64 + (size_t)kb * BLKSZ * HDIM;
            const __nv_bfloat16* vlp = g_vl + bh64 + (size_t)kb * BLKSZ * HDIM;
            for (int i = t; i < 512; i += 128) {
                int row = i >> 3, seg = (i & 7) * 8;
                int so = row * ATT_STRB + seg * 2, go = row * HDIM + seg;
                *(uint4*)(smraw + T_KH + so) = *(const uint4*)(khp + go);
                *(uint4*)(smraw + T_KL + so) = *(const uint4*)(klp + go);
                *(uint4*)(smraw + T_VH + so) = *(const uint4*)(vhp + go);
                *(uint4*)(smraw + T_VL + so) = *(const uint4*)(vlp + go);
            }
        }
        // ---- Fill penalty tiles ----
        if (band_tile) {
            const float* bmb = band_mask
                + ((size_t)(b * 60 + (qb - 3)) * 64) * 192 + (size_t)(it - 2) * 64;
            for (int i = t; i < 1024; i += 128) {
                int row = i >> 4, c4 = (i & 15) * 4;
                float4 mv = *(const float4*)(bmb + row * 192 + c4);
                float* d = pen2d + row * 68 + c4;
                d[0] = (1.f - mv.x) * pen; d[1] = (1.f - mv.y) * pen;
                d[2] = (1.f - mv.z) * pen; d[3] = (1.f - mv.w) * pen;
            }
        } else {
            if (t < 16) {
                float4 mv = *(const float4*)(to_mask + (size_t)b * SS + kb * BLKSZ + t * 4);
                pen1[t*4+0] = (1.f - mv.x) * pen; pen1[t*4+1] = (1.f - mv.y) * pen;
                pen1[t*4+2] = (1.f - mv.z) * pen; pen1[t*4+3] = (1.f - mv.w) * pen;
            }
        }
        __syncthreads();

        // ---- Scores: S = Q K^T (split precision) ----
        float acc[8][4];
#pragma unroll
        for (int nj = 0; nj < 8; nj++)
#pragma unroll
            for (int e = 0; e < 4; e++) acc[nj][e] = 0.f;

#pragma unroll
        for (int nj = 0; nj < 8; nj++) {
            uint32_t kh8[8], kl8[8];
            uint32_t rbase = (uint32_t)((nj * 8 + (lane & 7)) * ATT_STRB + (lane >> 3) * 16);
            ldsm_x4(kh8,     smem_base + T_KH + rbase);
            ldsm_x4(kh8 + 4, smem_base + T_KH + rbase + 64);
            ldsm_x4(kl8,     smem_base + T_KL + rbase);
            ldsm_x4(kl8 + 4, smem_base + T_KL + rbase + 64);
#pragma unroll
            for (int kk = 0; kk < 4; kk++) {
                mma_bf16(acc[nj], qfh[kk], kh8[2*kk], kh8[2*kk+1]);
                mma_bf16(acc[nj], qfh[kk], kl8[2*kk], kl8[2*kk+1]);
                mma_bf16(acc[nj], qfl[kk], kh8[2*kk], kh8[2*kk+1]);
            }
        }

        // ---- Scale + mask ----
        const int qr0 = wid * 16 + (lane >> 2);
#pragma unroll
        for (int nj = 0; nj < 8; nj++) {
#pragma unroll
            for (int e = 0; e < 4; e++) {
                int col = nj * 8 + (lane & 3) * 2 + (e & 1);
                float pe = band_tile
                    ? pen2d[(qr0 + (e >> 1) * 8) * 68 + col]
                    : pen1[col];
                acc[nj][e] = acc[nj][e] * rs + pe;
            }
        }

        // ---- Streaming softmax ----
        float tm0 = -1e30f, tm1 = -1e30f;
#pragma unroll
        for (int nj = 0; nj < 8; nj++) {
            tm0 = fmaxf(tm0, fmaxf(acc[nj][0], acc[nj][1]));
            tm1 = fmaxf(tm1, fmaxf(acc[nj][2], acc[nj][3]));
        }
        tm0 = fmaxf(tm0, __shfl_xor_sync(0xffffffffu, tm0, 1));
        tm0 = fmaxf(tm0, __shfl_xor_sync(0xffffffffu, tm0, 2));
        tm1 = fmaxf(tm1, __shfl_xor_sync(0xffffffffu, tm1, 1));
        tm1 = fmaxf(tm1, __shfl_xor_sync(0xffffffffu, tm1, 2));

        float nm0 = fmaxf(m0, tm0), nm1 = fmaxf(m1, tm1);
        float c0 = __expf(m0 - nm0), c1 = __expf(m1 - nm1);
        float ts0 = 0.f, ts1 = 0.f;
#pragma unroll
        for (int nj = 0; nj < 8; nj++) {
            acc[nj][0] = __expf(acc[nj][0] - nm0);
            acc[nj][1] = __expf(acc[nj][1] - nm0);
            acc[nj][2] = __expf(acc[nj][2] - nm1);
            acc[nj][3] = __expf(acc[nj][3] - nm1);
            ts0 += acc[nj][0] + acc[nj][1];
            ts1 += acc[nj][2] + acc[nj][3];
        }
        ts0 += __shfl_xor_sync(0xffffffffu, ts0, 1);
        ts0 += __shfl_xor_sync(0xffffffffu, ts0, 2);
        ts1 += __shfl_xor_sync(0xffffffffu, ts1, 1);
        ts1 += __shfl_xor_sync(0xffffffffu, ts1, 2);
        l0 = l0 * c0 + ts0;  l1 = l1 * c1 + ts1;
        m0 = nm0;  m1 = nm1;
#pragma unroll
        for (int nj = 0; nj < 8; nj++) {
            o[nj][0] *= c0; o[nj][1] *= c0;
            o[nj][2] *= c1; o[nj][3] *= c1;
        }

        // ---- Pack P -> A-frags (bf16 hi/lo) ----
        uint32_t phi[4][4], plo[4][4];
#pragma unroll
        for (int kk2 = 0; kk2 < 4; kk2++) {
            phi[kk2][0] = pack_hilo(acc[2*kk2][0],   acc[2*kk2][1],   plo[kk2][0]);
            phi[kk2][1] = pack_hilo(acc[2*kk2][2],   acc[2*kk2][3],   plo[kk2][1]);
            phi[kk2][2] = pack_hilo(acc[2*kk2+1][0], acc[2*kk2+1][1], plo[kk2][2]);
            phi[kk2][3] = pack_hilo(acc[2*kk2+1][2], acc[2*kk2+1][3], plo[kk2][3]);
        }

        // ---- PV: O += P V (split precision) ----
#pragma unroll
        for (int njd = 0; njd < 8; njd++) {
#pragma unroll
            for (int kk2 = 0; kk2 < 4; kk2++) {
                uint32_t vh[2], vl[2];
                uint32_t off = (uint32_t)((kk2 * 16 + (lane & 15)) * ATT_STRB + njd * 16);
                ldsm_x2_trans(vh, smem_base + T_VH + off);
                ldsm_x2_trans(vl, smem_base + T_VL + off);
                mma_bf16(o[njd], phi[kk2], vh[0], vh[1]);
                mma_bf16(o[njd], phi[kk2], vl[0], vl[1]);
                mma_bf16(o[njd], plo[kk2], vh[0], vh[1]);
            }
        }
        __syncthreads();
    }

    const int r0 = wid * 16 + (lane >> 2);
    if (!heavy) {
        // ---- light epilogue: ctx = O * from_mask / l, split bf16 hi/lo ----
        const int s0 = qb * BLKSZ + r0;
        const int s1 = s0 + 8;
        float inv0 = from_mask[(size_t)b * SS + s0] / l0;
        float inv1 = from_mask[(size_t)b * SS + s1] / l1;
#pragma unroll
        for (int njd = 0; njd < 8; njd++) {
            const int col = njd * 8 + (lane & 3) * 2;
            {
                size_t idx = ((size_t)b * SS + s0) * DD + h * HDIM + col;
                uint32_t lo, hi = pack_hilo(o[njd][0] * inv0, o[njd][1] * inv0, lo);
                *(uint32_t*)(g_c_hi + idx) = hi;
                *(uint32_t*)(g_c_lo + idx) = lo;
            }
            {
                size_t idx = ((size_t)b * SS + s1) * DD + h * HDIM + col;
                uint32_t lo, hi = pack_hilo(o[njd][2] * inv1, o[njd][3] * inv1, lo);
                *(uint32_t*)(g_c_hi + idx) = hi;
                *(uint32_t*)(g_c_lo + idx) = lo;
            }
        }
    } else {
        // ---- heavy epilogue: write unnormalized partials + m, l ----
        const int cid = ((b * HH + h) * 2 + qb) * 8 + ch;
        float* pob = g_po + (size_t)cid * 4096;
#pragma unroll
        for (int njd = 0; njd < 8; njd++) {
            const int col = njd * 8 + (lane & 3) * 2;
            float2 s0v; s0v.x = o[njd][0]; s0v.y = o[njd][1];
            float2 s1v; s1v.x = o[njd][2]; s1v.y = o[njd][3];
            *(float2*)(pob + r0 * 64 + col) = s0v;
            *(float2*)(pob + (r0 + 8) * 64 + col) = s1v;
        }
        if ((lane & 3) == 0) {
            g_pm[cid * 64 + r0]     = m0;
            g_pm[cid * 64 + r0 + 8] = m1;
            g_pl[cid * 64 + r0]     = l0;
            g_pl[cid * 64 + r0 + 8] = l1;
        }
    }
}

// ---------------------------------------------------------------------------
// Combine split-KV partials for heavy q-blocks.
// grid 64 = (b*16+h)*2+qb; 128 threads: r = t>>1, half = t&1 (32 cols).
// ---------------------------------------------------------------------------
__global__ __launch_bounds__(128) void attn_combine(const float* __restrict__ from_mask)
{
    const int x  = blockIdx.x;
    const int qb = x & 1;
    const int h  = (x >> 1) & 15;
    const int b  = x >> 5;
    const int t  = threadIdx.x;
    const int r  = t >> 1;
    const int c0 = (t & 1) * 32;
    const int base8 = x * 8;

    float m[8], l[8], M = -1e30f;
#pragma unroll
    for (int i = 0; i < 8; i++) {
        m[i] = g_pm[(base8 + i) * 64 + r];
        l[i] = g_pl[(base8 + i) * 64 + r];
        M = fmaxf(M, m[i]);
    }
    float L = 0.f, sc[8];
#pragma unroll
    for (int i = 0; i < 8; i++) { sc[i] = __expf(m[i] - M); L += l[i] * sc[i]; }

    float acc[32];
#pragma unroll
    for (int c = 0; c < 32; c++) acc[c] = 0.f;
#pragma unroll
    for (int i = 0; i < 8; i++) {
        const float* p = g_po + (size_t)(base8 + i) * 4096 + r * 64 + c0;
        float s = sc[i];
#pragma unroll
        for (int c4 = 0; c4 < 8; c4++) {
            float4 v = *(const float4*)(p + c4 * 4);
            acc[c4*4+0] += s * v.x; acc[c4*4+1] += s * v.y;
            acc[c4*4+2] += s * v.z; acc[c4*4+3] += s * v.w;
        }
    }

    const int s_ = qb * BLKSZ + r;
    float inv = from_mask[(size_t)b * SS + s_] / L;
    size_t idx = ((size_t)b * SS + s_) * DD + h * HDIM + c0;
#pragma unroll
    for (int c = 0; c < 32; c += 2) {
        uint32_t lo, hi = pack_hilo(acc[c] * inv, acc[c+1] * inv, lo);
        *(uint32_t*)(g_c_hi + idx + c) = hi;
        *(uint32_t*)(g_c_lo + idx + c) = lo;
    }
}

// ---------------------------------------------------------------------------
extern "C" void kernel_launch(void* const* d_in, const int* in_sizes, int n_in,
                              void* d_out, int out_size)
{
    const float* tokens    = (const float*)d_in[0];
    const float* band_mask = (const float*)d_in[1];
    const float* from_mask = (const float*)d_in[2];
    const float* to_mask   = (const float*)d_in[3];
    const float* Wq        = (const float*)d_in[4];
    const float* Wk        = (const float*)d_in[5];
    const float* Wv        = (const float*)d_in[6];
    const float* Wu        = (const float*)d_in[7];
    const float* bu        = (const float*)d_in[8];
    float* out = (float*)d_out;

    cudaFuncSetAttribute(attn_kernel,
                         cudaFuncAttributeMaxDynamicSharedMemorySize, ATTN_SMEM_BYTES);
    cudaFuncSetAttribute(gemm_hmma_kernel,
                         cudaFuncAttributeMaxDynamicSharedMemorySize, GEMM_SMEM_BYTES);

    // 0) Precision-split inputs and weights
    split_x_kernel<<<(MROWS * DD / 4) / 256, 256>>>(tokens);
    wsplit_kernel<<<dim3(1024, 4), 256>>>(Wq, Wk, Wv, Wu);

    // 1) QKV projections (double-buffered HMMA, grid.z = q/k/v)
    gemm_hmma_kernel<<<dim3(8, 64, 3), 256, GEMM_SMEM_BYTES>>>(0, nullptr, nullptr);

    // 2) Sparse attention (light + split-KV heavy in one grid)
    attn_kernel<<<dim3(78, HH, BB), 128, ATTN_SMEM_BYTES>>>(band_mask, from_mask, to_mask);

    // 2b) Combine heavy partials
    attn_combine<<<64, 128>>>(from_mask);

    // 3) Output projection + bias (double-buffered HMMA)
    gemm_hmma_kernel<<<dim3(8, 64, 1), 256, GEMM_SMEM_BYTES>>>(3, bu, out);
}